// round 16
// baseline (speedup 1.0000x reference)
#include <cuda_runtime.h>
#include <cuda_fp16.h>
#include <math.h>

#define NMAX 100000
#define EMAX 1600000
#define CH   128
#define HEADS 4
#define FEAT 32
#define GMAX 512
#define NEG_SLOPE 0.2f
#define BN_EPS 1e-5f
#define SCAN_CHUNK 1024
#define A_STR 132   // padded row stride (floats) for A smem

// ---------------- device scratch ----------------
__device__ __half g_hh[NMAX * CH];   // GEMM output h (fp16) — attention payload
__device__ __half g_ah[NMAX * CH];   // layer1 activations (fp16, pre-BN)
__device__ float g_es [NMAX * HEADS];
__device__ float g_ed [NMAX * HEADS];
__device__ float g_z  [NMAX * FEAT];
__device__ float g_bnsum1[CH];
__device__ float g_bnsq1 [CH];
__device__ float g_bnsum2[FEAT];
__device__ float g_bnsq2 [FEAT];
__device__ float g_sc1[CH],  g_sh1[CH];
__device__ float g_sc2[FEAT], g_sh2[FEAT];
__device__ float g_pool[GMAX * FEAT];
__device__ float g_cnt [GMAX];
// CSR
__device__ int g_deg[NMAX];
__device__ int g_blocksum[128];
__device__ int g_blockoff[128];
__device__ int g_rowptr[NMAX + 1];
__device__ int g_work[NMAX];
__device__ int g_csr[EMAX];

// ---------------- helpers ----------------
__device__ __forceinline__ float lrelu(float x) { return x >= 0.f ? x : NEG_SLOPE * x; }
__device__ __forceinline__ float elu_f(float x) { return x > 0.f ? x : expm1f(x); }

__device__ __forceinline__ void red_add_v4(float* p, float4 v) {
    asm volatile("red.global.add.v4.f32 [%0], {%1,%2,%3,%4};"
                 :: "l"(p), "f"(v.x), "f"(v.y), "f"(v.z), "f"(v.w) : "memory");
}

__device__ __forceinline__ unsigned f2tf32(float v) {
    unsigned u;
    asm("cvt.rna.tf32.f32 %0, %1;" : "=r"(u) : "f"(v));
    return u;
}

__device__ __forceinline__ float4 ld_h4(const __half* p) {
    uint2 raw = *(const uint2*)p;
    float2 fa = __half22float2(*(__half2*)&raw.x);
    float2 fb = __half22float2(*(__half2*)&raw.y);
    return make_float4(fa.x, fa.y, fb.x, fb.y);
}

__device__ __forceinline__ void st_h4(__half* p, float4 v) {
    __half2 h0 = __floats2half2_rn(v.x, v.y);
    __half2 h1 = __floats2half2_rn(v.z, v.w);
    uint2 u;
    u.x = *(unsigned*)&h0; u.y = *(unsigned*)&h1;
    *(uint2*)p = u;
}

// ---------------- zero / CSR build ----------------
__global__ void k_zero(int n) {
    int i = blockIdx.x * blockDim.x + threadIdx.x;
    if (i < n)           g_deg[i] = 0;
    if (i < GMAX * FEAT) g_pool[i] = 0.f;
    if (i < GMAX)        g_cnt[i] = 0.f;
    if (i < CH)   { g_bnsum1[i] = 0.f; g_bnsq1[i] = 0.f; }
    if (i < FEAT) { g_bnsum2[i] = 0.f; g_bnsq2[i] = 0.f; }
}

__global__ void k_hist(const int* __restrict__ dst, int E) {
    int e = blockIdx.x * blockDim.x + threadIdx.x;
    if (e < E) atomicAdd(&g_deg[dst[e]], 1);
}

__global__ void k_scan1(int n) {
    __shared__ int wsum[32];
    int t = threadIdx.x;
    int i = blockIdx.x * SCAN_CHUNK + t;
    int l = t & 31, w = t >> 5;
    int v = (i < n) ? g_deg[i] : 0;
    int x = v;
#pragma unroll
    for (int off = 1; off < 32; off <<= 1) {
        int u = __shfl_up_sync(0xffffffffu, x, off);
        if (l >= off) x += u;
    }
    if (l == 31) wsum[w] = x;
    __syncthreads();
    if (w == 0) {
        int y = wsum[l];
#pragma unroll
        for (int off = 1; off < 32; off <<= 1) {
            int u = __shfl_up_sync(0xffffffffu, y, off);
            if (l >= off) y += u;
        }
        wsum[l] = y;
    }
    __syncthreads();
    if (w > 0) x += wsum[w - 1];
    if (i < n) g_deg[i] = x;
    if (t == SCAN_CHUNK - 1) g_blocksum[blockIdx.x] = x;
}

__global__ void k_scan2(int B) {
    int l = threadIdx.x;          // 32 threads
    int base = l * 4;
    int v0 = (base + 0 < B) ? g_blocksum[base + 0] : 0;
    int v1 = (base + 1 < B) ? g_blocksum[base + 1] : 0;
    int v2 = (base + 2 < B) ? g_blocksum[base + 2] : 0;
    int v3 = (base + 3 < B) ? g_blocksum[base + 3] : 0;
    int s1 = v0, s2 = s1 + v1, s3 = s2 + v2, s4 = s3 + v3;
    int x = s4;
#pragma unroll
    for (int off = 1; off < 32; off <<= 1) {
        int u = __shfl_up_sync(0xffffffffu, x, off);
        if (l >= off) x += u;
    }
    int ex = x - s4;
    g_blockoff[base + 0] = ex;
    g_blockoff[base + 1] = ex + s1;
    g_blockoff[base + 2] = ex + s2;
    g_blockoff[base + 3] = ex + s3;
}

__global__ void k_scan3(int n) {
    int i = blockIdx.x * blockDim.x + threadIdx.x;
    if (i > n) return;
    int val = (i == 0) ? 0 : g_deg[i - 1] + g_blockoff[(i - 1) >> 10];
    g_rowptr[i] = val;
    if (i < n) g_work[i] = val;
}

__global__ void k_scatter(const int* __restrict__ src, const int* __restrict__ dst, int E) {
    int e = blockIdx.x * blockDim.x + threadIdx.x;
    if (e >= E) return;
    int d = dst[e];
    int p = atomicAdd(&g_work[d], 1);
    g_csr[p] = src[e];
}

// ---------------- tf32 MMA GEMM: conflict-free smem, fused act-in + es/ed epilogue ----------------
// ACT=false: X is fp32 (raw input). ACT=true: X is fp16 (layer1 activations) + BN+ELU fused.
template<bool ACT>
__global__ void __launch_bounds__(256, 1)
k_gemm(const void* __restrict__ Xv, const float* __restrict__ W,
       const float* __restrict__ sc, const float* __restrict__ sh,
       const float* __restrict__ a_src, const float* __restrict__ a_dst,
       __half* __restrict__ Y, int n) {
    extern __shared__ float smf[];
    float*    a_s   = smf;                         // 128 * A_STR floats
    unsigned* b_buf = (unsigned*)(smf + 128 * A_STR);  // 16384 u32
    float*    s_as  = (float*)(b_buf + 16384);     // 128
    float*    s_ad  = s_as + 128;                  // 128
    int t = threadIdx.x;
    int rb = blockIdx.x * 128;
    const float4* W4 = (const float4*)W;

    if (t < 128) { s_as[t] = a_src[t]; s_ad[t] = a_dst[t]; }

#pragma unroll
    for (int i = 0; i < 16; i++) {
        int q = i * 256 + t;
        int row = q >> 5, c4 = (q & 31) * 4;
        float4 v = make_float4(0.f, 0.f, 0.f, 0.f);
        if (rb + row < n) {
            if (ACT) {
                const __half* Xh = (const __half*)Xv;
                v = ld_h4(&Xh[(long)(rb + row) * CH + c4]);
                v.x = elu_f(sc[c4 + 0] * v.x + sh[c4 + 0]);
                v.y = elu_f(sc[c4 + 1] * v.y + sh[c4 + 1]);
                v.z = elu_f(sc[c4 + 2] * v.z + sh[c4 + 2]);
                v.w = elu_f(sc[c4 + 3] * v.w + sh[c4 + 3]);
            } else {
                v = ((const float4*)Xv)[(long)(rb + row) * 32 + (q & 31)];
            }
        }
        float4 tv;
        tv.x = __uint_as_float(f2tf32(v.x));
        tv.y = __uint_as_float(f2tf32(v.y));
        tv.z = __uint_as_float(f2tf32(v.z));
        tv.w = __uint_as_float(f2tf32(v.w));
        *(float4*)&a_s[row * A_STR + c4] = tv;
    }
#pragma unroll
    for (int i = 0; i < 16; i++) {
        int q = i * 256 + t;
        int k = q >> 5, c4 = (q & 31) * 4;
        float4 v = W4[q];
        const float* vf = (const float*)&v;
#pragma unroll
        for (int e = 0; e < 4; e++) {
            int ncol = c4 + e;
            int tile = (k >> 3) * 16 + (ncol >> 3);
            int lf = ((ncol & 7) << 2) | (k & 3);
            int j = (k & 7) >= 4 ? 1 : 0;
            int off = (lf * 2 + j) ^ ((tile & 15) << 1);
            b_buf[tile * 64 + off] = f2tf32(vf[e]);
        }
    }
    __syncthreads();

    int w = t >> 5, l = t & 31;
    int gr = l >> 2, gc = l & 3;
    float d[16][4];
#pragma unroll
    for (int nb = 0; nb < 16; nb++)
#pragma unroll
        for (int j = 0; j < 4; j++) d[nb][j] = 0.f;

    int arow = (w * 16 + gr) * A_STR + gc;
    for (int kb = 0; kb < 16; kb++) {
        int ab = arow + kb * 8;
        unsigned a0 = __float_as_uint(a_s[ab]);
        unsigned a1 = __float_as_uint(a_s[ab + 8 * A_STR]);
        unsigned a2 = __float_as_uint(a_s[ab + 4]);
        unsigned a3 = __float_as_uint(a_s[ab + 8 * A_STR + 4]);
#pragma unroll
        for (int nb = 0; nb < 16; nb++) {
            int tile = kb * 16 + nb;
            uint2 b = *(const uint2*)&b_buf[tile * 64 + ((l * 2) ^ (nb << 1))];
            asm volatile(
                "mma.sync.aligned.m16n8k8.row.col.f32.tf32.tf32.f32 "
                "{%0,%1,%2,%3}, {%4,%5,%6,%7}, {%8,%9}, {%0,%1,%2,%3};"
                : "+f"(d[nb][0]), "+f"(d[nb][1]), "+f"(d[nb][2]), "+f"(d[nb][3])
                : "r"(a0), "r"(a1), "r"(a2), "r"(a3), "r"(b.x), "r"(b.y));
        }
    }

    int r0g = rb + w * 16 + gr;
    int r1g = r0g + 8;
    int cb0 = gc * 2;
    float es0[4], es1[4], ed0[4], ed1[4];
#pragma unroll
    for (int hh = 0; hh < 4; hh++) { es0[hh] = 0.f; es1[hh] = 0.f; ed0[hh] = 0.f; ed1[hh] = 0.f; }
#pragma unroll
    for (int nb = 0; nb < 16; nb++) {
        int colb = nb * 8 + cb0;
        int hh = nb >> 2;
        float a0 = s_as[colb], a1 = s_as[colb + 1];
        float b0 = s_ad[colb], b1 = s_ad[colb + 1];
        es0[hh] += d[nb][0] * a0 + d[nb][1] * a1;
        es1[hh] += d[nb][2] * a0 + d[nb][3] * a1;
        ed0[hh] += d[nb][0] * b0 + d[nb][1] * b1;
        ed1[hh] += d[nb][2] * b0 + d[nb][3] * b1;
    }
#pragma unroll
    for (int o = 1; o <= 2; o <<= 1) {
#pragma unroll
        for (int hh = 0; hh < 4; hh++) {
            es0[hh] += __shfl_xor_sync(0xffffffffu, es0[hh], o);
            es1[hh] += __shfl_xor_sync(0xffffffffu, es1[hh], o);
            ed0[hh] += __shfl_xor_sync(0xffffffffu, ed0[hh], o);
            ed1[hh] += __shfl_xor_sync(0xffffffffu, ed1[hh], o);
        }
    }
    if (gc == 0) {
        if (r0g < n) {
            *(float4*)&g_es[r0g * HEADS] = make_float4(es0[0], es0[1], es0[2], es0[3]);
            *(float4*)&g_ed[r0g * HEADS] = make_float4(ed0[0], ed0[1], ed0[2], ed0[3]);
        }
        if (r1g < n) {
            *(float4*)&g_es[r1g * HEADS] = make_float4(es1[0], es1[1], es1[2], es1[3]);
            *(float4*)&g_ed[r1g * HEADS] = make_float4(ed1[0], ed1[1], ed1[2], ed1[3]);
        }
    }
    bool st0 = r0g < n, st1 = r1g < n;
#pragma unroll
    for (int nb = 0; nb < 16; nb++) {
        int colb = nb * 8 + cb0;
        if (st0) {
            __half2 hv = __floats2half2_rn(d[nb][0], d[nb][1]);
            *(unsigned*)&Y[(long)r0g * CH + colb] = *(unsigned*)&hv;
        }
        if (st1) {
            __half2 hv = __floats2half2_rn(d[nb][2], d[nb][3]);
            *(unsigned*)&Y[(long)r1g * CH + colb] = *(unsigned*)&hv;
        }
    }
}

// ---------------- persistent warp-per-dst attention + fused finalize (R9 body; fp16 acc out) ----------------
template<int LAYER>
__global__ void __launch_bounds__(256)
k_attn(const __half* __restrict__ h, const float* __restrict__ bias,
       float* __restrict__ bnsum, float* __restrict__ bnsq,
       int n, int nwarps) {
    __shared__ int   s_idx[8][32];
    __shared__ float s_w  [8][128];
    int wb = threadIdx.x >> 5, l = threadIdx.x & 31;
    int gw = blockIdx.x * 8 + wb;
    int hsel = l >> 3, cg = l * 4;
    float bs[4] = {0.f, 0.f, 0.f, 0.f};
    float bq[4] = {0.f, 0.f, 0.f, 0.f};

    for (int d = gw; d < n; d += nwarps) {
        int beg = g_rowptr[d], end = g_rowptr[d + 1];
        float4 ed4 = *(const float4*)&g_ed[d * HEADS];
        float4 esd = *(const float4*)&g_es[d * HEADS];
        float4 wsf;
        wsf.x = __expf(lrelu(esd.x + ed4.x));
        wsf.y = __expf(lrelu(esd.y + ed4.y));
        wsf.z = __expf(lrelu(esd.z + ed4.z));
        wsf.w = __expf(lrelu(esd.w + ed4.w));
        float wsh = hsel == 0 ? wsf.x : hsel == 1 ? wsf.y : hsel == 2 ? wsf.z : wsf.w;
        float4 acc = ld_h4(&h[(long)d * CH + cg]);
        acc.x *= wsh; acc.y *= wsh; acc.z *= wsh; acc.w *= wsh;
        float4 den = (l == 0) ? wsf : make_float4(0.f, 0.f, 0.f, 0.f);

        for (int j0 = beg; j0 < end; j0 += 32) {
            int j = j0 + l;
            int s = 0;
            float4 w4 = make_float4(0.f, 0.f, 0.f, 0.f);
            if (j < end) {
                s = g_csr[j];
                float4 es4 = *(const float4*)&g_es[s * HEADS];
                w4.x = __expf(lrelu(es4.x + ed4.x));
                w4.y = __expf(lrelu(es4.y + ed4.y));
                w4.z = __expf(lrelu(es4.z + ed4.z));
                w4.w = __expf(lrelu(es4.w + ed4.w));
            }
            den.x += w4.x; den.y += w4.y; den.z += w4.z; den.w += w4.w;
            s_idx[wb][l] = s;
            *(float4*)&s_w[wb][l * 4] = w4;
            __syncwarp();
            int kmax = min(32, end - j0);
#pragma unroll 4
            for (int k = 0; k < kmax; k++) {
                int   sk = s_idx[wb][k];
                float w  = s_w[wb][k * 4 + hsel];
                float4 hv = ld_h4(&h[(long)sk * CH + cg]);
                acc.x += w * hv.x; acc.y += w * hv.y;
                acc.z += w * hv.z; acc.w += w * hv.w;
            }
            __syncwarp();
        }
#pragma unroll
        for (int o = 16; o; o >>= 1) {
            den.x += __shfl_xor_sync(0xffffffffu, den.x, o);
            den.y += __shfl_xor_sync(0xffffffffu, den.y, o);
            den.z += __shfl_xor_sync(0xffffffffu, den.z, o);
            den.w += __shfl_xor_sync(0xffffffffu, den.w, o);
        }
        float dh = hsel == 0 ? den.x : hsel == 1 ? den.y : hsel == 2 ? den.z : den.w;
        float rd = 1.f / dh;
        if (LAYER == 1) {
            float4 b4 = *(const float4*)&bias[cg];
            float4 v;
            v.x = acc.x * rd + b4.x; v.y = acc.y * rd + b4.y;
            v.z = acc.z * rd + b4.z; v.w = acc.w * rd + b4.w;
            st_h4(&g_ah[(long)d * CH + cg], v);    // fp16 layer-boundary store
            bs[0] += v.x; bs[1] += v.y; bs[2] += v.z; bs[3] += v.w;
            bq[0] += v.x * v.x; bq[1] += v.y * v.y; bq[2] += v.z * v.z; bq[3] += v.w * v.w;
        } else {
            float4 v;
            v.x = acc.x * rd; v.y = acc.y * rd; v.z = acc.z * rd; v.w = acc.w * rd;
#pragma unroll
            for (int o = 8; o <= 16; o <<= 1) {
                v.x += __shfl_xor_sync(0xffffffffu, v.x, o);
                v.y += __shfl_xor_sync(0xffffffffu, v.y, o);
                v.z += __shfl_xor_sync(0xffffffffu, v.z, o);
                v.w += __shfl_xor_sync(0xffffffffu, v.w, o);
            }
            if (l < 8) {
                float4 b4 = *(const float4*)&bias[l * 4];
                v.x = 0.25f * v.x + b4.x; v.y = 0.25f * v.y + b4.y;
                v.z = 0.25f * v.z + b4.z; v.w = 0.25f * v.w + b4.w;
                *(float4*)&g_z[(long)d * FEAT + l * 4] = v;
                bs[0] += v.x; bs[1] += v.y; bs[2] += v.z; bs[3] += v.w;
                bq[0] += v.x * v.x; bq[1] += v.y * v.y; bq[2] += v.z * v.z; bq[3] += v.w * v.w;
            }
        }
    }
    if (LAYER == 1 || l < 8) {
        int c0 = (LAYER == 1) ? cg : l * 4;
#pragma unroll
        for (int j = 0; j < 4; j++) {
            atomicAdd(&bnsum[c0 + j], bs[j]);
            atomicAdd(&bnsq [c0 + j], bq[j]);
        }
    }
}

// ---------------- BN scale/shift prep ----------------
__global__ void k_bnprep(const float* __restrict__ gamma, const float* __restrict__ beta,
                         const float* __restrict__ bnsum, const float* __restrict__ bnsq,
                         float* __restrict__ sc, float* __restrict__ sh,
                         int C, float inv_n) {
    int c = threadIdx.x;
    if (c >= C) return;
    float mean = bnsum[c] * inv_n;
    float var  = bnsq[c] * inv_n - mean * mean;
    float g = gamma[c] * rsqrtf(var + BN_EPS);
    sc[c] = g;
    sh[c] = beta[c] - mean * g;
}

// ---------------- pool with fused BN+ELU ----------------
__global__ void k_pool(const int* __restrict__ batch, int n) {
    int i = blockIdx.x * blockDim.x + threadIdx.x;
    if (i >= n) return;
    int g = batch[i];
    const float4* zp = (const float4*)&g_z[(long)i * FEAT];
#pragma unroll
    for (int c = 0; c < 8; c++) {
        float4 z = zp[c];
        int c0 = c * 4;
        z.x = elu_f(g_sc2[c0 + 0] * z.x + g_sh2[c0 + 0]);
        z.y = elu_f(g_sc2[c0 + 1] * z.y + g_sh2[c0 + 1]);
        z.z = elu_f(g_sc2[c0 + 2] * z.z + g_sh2[c0 + 2]);
        z.w = elu_f(g_sc2[c0 + 3] * z.w + g_sh2[c0 + 3]);
        red_add_v4(&g_pool[g * FEAT + c0], z);
    }
    atomicAdd(&g_cnt[g], 1.f);
}

__global__ void k_final(const float* __restrict__ Wl, const float* __restrict__ bl,
                        float* __restrict__ out, int G) {
    int idx = blockIdx.x * blockDim.x + threadIdx.x;
    if (idx >= G * 2) return;
    int g = idx >> 1, o = idx & 1;
    float cn = fmaxf(g_cnt[g], 1.f);
    float s = bl[o];
#pragma unroll
    for (int f = 0; f < FEAT; f++)
        s += (g_pool[g * FEAT + f] / cn) * Wl[f * 2 + o];
    out[idx] = s;
}

// ---------------- host launch ----------------
extern "C" void kernel_launch(void* const* d_in, const int* in_sizes, int n_in,
                              void* d_out, int out_size) {
    const float* x   = (const float*)d_in[0];
    const int*   ei  = (const int*)  d_in[1];
    const int*   bat = (const int*)  d_in[2];
    const float* W1  = (const float*)d_in[3];
    const float* as1 = (const float*)d_in[4];
    const float* ad1 = (const float*)d_in[5];
    const float* b1  = (const float*)d_in[6];
    const float* g1  = (const float*)d_in[7];
    const float* be1 = (const float*)d_in[8];
    const float* W2  = (const float*)d_in[9];
    const float* as2 = (const float*)d_in[10];
    const float* ad2 = (const float*)d_in[11];
    const float* b2  = (const float*)d_in[12];
    const float* g2  = (const float*)d_in[13];
    const float* be2 = (const float*)d_in[14];
    const float* Wl  = (const float*)d_in[15];
    const float* bl  = (const float*)d_in[16];
    float* out = (float*)d_out;

    int n = in_sizes[0] / CH;   // 100000
    int E = in_sizes[1] / 2;    // 1600000
    int G = out_size / 2;       // 512
    const int* esrc = ei;
    const int* edst = ei + E;

    static __half *phh = nullptr, *pah = nullptr;
    static float *psc1, *psh1, *psc2, *psh2;
    static float *pbs1, *pbq1, *pbs2, *pbq2;
    static cudaStream_t s2;
    static cudaEvent_t ev_fork, ev_join;
    static bool configured = false;
    size_t gsmem = (size_t)128 * A_STR * 4 + 16384 * 4 + 256 * 4;  // ~134 KB
    if (!configured) {
        cudaGetSymbolAddress((void**)&phh,  g_hh);
        cudaGetSymbolAddress((void**)&pah,  g_ah);
        cudaGetSymbolAddress((void**)&psc1, g_sc1);
        cudaGetSymbolAddress((void**)&psh1, g_sh1);
        cudaGetSymbolAddress((void**)&psc2, g_sc2);
        cudaGetSymbolAddress((void**)&psh2, g_sh2);
        cudaGetSymbolAddress((void**)&pbs1, g_bnsum1);
        cudaGetSymbolAddress((void**)&pbq1, g_bnsq1);
        cudaGetSymbolAddress((void**)&pbs2, g_bnsum2);
        cudaGetSymbolAddress((void**)&pbq2, g_bnsq2);
        cudaFuncSetAttribute(k_gemm<false>, cudaFuncAttributeMaxDynamicSharedMemorySize, (int)gsmem);
        cudaFuncSetAttribute(k_gemm<true>,  cudaFuncAttributeMaxDynamicSharedMemorySize, (int)gsmem);
        cudaStreamCreateWithFlags(&s2, cudaStreamNonBlocking);
        cudaEventCreateWithFlags(&ev_fork, cudaEventDisableTiming);
        cudaEventCreateWithFlags(&ev_join, cudaEventDisableTiming);
        configured = true;
    }

    float inv_n = 1.f / (float)n;
    int nb_node = (n + 255) / 256;
    int nb_edge = (E + 255) / 256;
    int nb_gemm = (n + 127) / 128;
    int nb_attn = 592;                     // 4 blocks/SM x 148 (proven best)
    int nwarps  = nb_attn * 8;
    int B_scan  = (n + SCAN_CHUNK - 1) / SCAN_CHUNK;

    // zero, then fork: CSR build on s2 || GEMM-1 on main stream (R9 schedule)
    k_zero<<<nb_node, 256>>>(n);
    cudaEventRecord(ev_fork, 0);
    cudaStreamWaitEvent(s2, ev_fork, 0);
    k_hist   <<<nb_edge, 256, 0, s2>>>(edst, E);
    k_scan1  <<<B_scan, SCAN_CHUNK, 0, s2>>>(n);
    k_scan2  <<<1, 32, 0, s2>>>(B_scan);
    k_scan3  <<<(n + 256) / 256, 256, 0, s2>>>(n);
    k_scatter<<<nb_edge, 256, 0, s2>>>(esrc, edst, E);
    cudaEventRecord(ev_join, s2);

    // ---- layer 1 ----
    k_gemm<false><<<nb_gemm, 256, gsmem>>>(x, W1, nullptr, nullptr, as1, ad1, phh, n);
    cudaStreamWaitEvent(0, ev_join, 0);
    k_attn<1><<<nb_attn, 256>>>(phh, b1, pbs1, pbq1, n, nwarps);
    k_bnprep<<<1, CH>>>(g1, be1, pbs1, pbq1, psc1, psh1, CH, inv_n);

    // ---- layer 2 (fp16 activations in, BN+ELU fused into GEMM load) ----
    k_gemm<true><<<nb_gemm, 256, gsmem>>>(pah, W2, psc1, psh1, as2, ad2, phh, n);
    k_attn<2><<<nb_attn, 256>>>(phh, b2, pbs2, pbq2, n, nwarps);
    k_bnprep<<<1, FEAT>>>(g2, be2, pbs2, pbq2, psc2, psh2, FEAT, inv_n);

    // ---- pool (BN+ELU fused) + linear ----
    k_pool<<<nb_node, 256>>>(bat, n);
    k_final<<<(G * 2 + 255) / 256, 256>>>(Wl, bl, out, G);
}

// round 17
// speedup vs baseline: 1.0052x; 1.0052x over previous
#include <cuda_runtime.h>
#include <cuda_fp16.h>
#include <math.h>

#define NMAX 100000
#define EMAX 1600000
#define CH   128
#define HEADS 4
#define FEAT 32
#define GMAX 512
#define NEG_SLOPE 0.2f
#define BN_EPS 1e-5f
#define SCAN_CHUNK 1024
#define A_STR 132   // padded row stride (floats) for A smem

// ---------------- device scratch ----------------
__device__ __half g_hh[NMAX * CH];   // GEMM output h (fp16) — attention payload
__device__ float g_acc[NMAX * CH];   // layer1 activations (fp32, pre-BN)
__device__ float g_es [NMAX * HEADS];
__device__ float g_ed [NMAX * HEADS];
__device__ float g_z  [NMAX * FEAT];
__device__ float g_bnsum1[CH];
__device__ float g_bnsq1 [CH];
__device__ float g_bnsum2[FEAT];
__device__ float g_bnsq2 [FEAT];
__device__ float g_sc1[CH],  g_sh1[CH];
__device__ float g_sc2[FEAT], g_sh2[FEAT];
__device__ float g_pool[GMAX * FEAT];
__device__ float g_cnt [GMAX];
// CSR
__device__ int g_deg[NMAX];
__device__ int g_blocksum[128];
__device__ int g_blockoff[128];
__device__ int g_rowptr[NMAX + 1];
__device__ int g_work[NMAX];
__device__ int g_csr[EMAX];

// ---------------- helpers ----------------
__device__ __forceinline__ float lrelu(float x) { return x >= 0.f ? x : NEG_SLOPE * x; }
__device__ __forceinline__ float elu_f(float x) { return x > 0.f ? x : expm1f(x); }

__device__ __forceinline__ void red_add_v4(float* p, float4 v) {
    asm volatile("red.global.add.v4.f32 [%0], {%1,%2,%3,%4};"
                 :: "l"(p), "f"(v.x), "f"(v.y), "f"(v.z), "f"(v.w) : "memory");
}

__device__ __forceinline__ unsigned f2tf32(float v) {
    unsigned u;
    asm("cvt.rna.tf32.f32 %0, %1;" : "=r"(u) : "f"(v));
    return u;
}

__device__ __forceinline__ float4 ld_h4(const __half* p) {
    uint2 raw = *(const uint2*)p;
    float2 fa = __half22float2(*(__half2*)&raw.x);
    float2 fb = __half22float2(*(__half2*)&raw.y);
    return make_float4(fa.x, fa.y, fb.x, fb.y);
}

// ---------------- zero (split by consumer) / CSR build ----------------
__global__ void k_zero_deg(int n) {
    int i = blockIdx.x * blockDim.x + threadIdx.x;
    if (i < n) g_deg[i] = 0;
}

__global__ void k_zero_rest() {
    int i = blockIdx.x * blockDim.x + threadIdx.x;
    if (i < GMAX * FEAT) g_pool[i] = 0.f;
    if (i < GMAX)        g_cnt[i] = 0.f;
    if (i < CH)   { g_bnsum1[i] = 0.f; g_bnsq1[i] = 0.f; }
    if (i < FEAT) { g_bnsum2[i] = 0.f; g_bnsq2[i] = 0.f; }
}

__global__ void k_hist(const int* __restrict__ dst, int E) {
    int e = blockIdx.x * blockDim.x + threadIdx.x;
    if (e < E) atomicAdd(&g_deg[dst[e]], 1);
}

__global__ void k_scan1(int n) {
    __shared__ int wsum[32];
    int t = threadIdx.x;
    int i = blockIdx.x * SCAN_CHUNK + t;
    int l = t & 31, w = t >> 5;
    int v = (i < n) ? g_deg[i] : 0;
    int x = v;
#pragma unroll
    for (int off = 1; off < 32; off <<= 1) {
        int u = __shfl_up_sync(0xffffffffu, x, off);
        if (l >= off) x += u;
    }
    if (l == 31) wsum[w] = x;
    __syncthreads();
    if (w == 0) {
        int y = wsum[l];
#pragma unroll
        for (int off = 1; off < 32; off <<= 1) {
            int u = __shfl_up_sync(0xffffffffu, y, off);
            if (l >= off) y += u;
        }
        wsum[l] = y;
    }
    __syncthreads();
    if (w > 0) x += wsum[w - 1];
    if (i < n) g_deg[i] = x;
    if (t == SCAN_CHUNK - 1) g_blocksum[blockIdx.x] = x;
}

__global__ void k_scan2(int B) {
    int l = threadIdx.x;          // 32 threads
    int base = l * 4;
    int v0 = (base + 0 < B) ? g_blocksum[base + 0] : 0;
    int v1 = (base + 1 < B) ? g_blocksum[base + 1] : 0;
    int v2 = (base + 2 < B) ? g_blocksum[base + 2] : 0;
    int v3 = (base + 3 < B) ? g_blocksum[base + 3] : 0;
    int s1 = v0, s2 = s1 + v1, s3 = s2 + v2, s4 = s3 + v3;
    int x = s4;
#pragma unroll
    for (int off = 1; off < 32; off <<= 1) {
        int u = __shfl_up_sync(0xffffffffu, x, off);
        if (l >= off) x += u;
    }
    int ex = x - s4;
    g_blockoff[base + 0] = ex;
    g_blockoff[base + 1] = ex + s1;
    g_blockoff[base + 2] = ex + s2;
    g_blockoff[base + 3] = ex + s3;
}

__global__ void k_scan3(int n) {
    int i = blockIdx.x * blockDim.x + threadIdx.x;
    if (i > n) return;
    int val = (i == 0) ? 0 : g_deg[i - 1] + g_blockoff[(i - 1) >> 10];
    g_rowptr[i] = val;
    if (i < n) g_work[i] = val;
}

__global__ void k_scatter(const int* __restrict__ src, const int* __restrict__ dst, int E) {
    int e = blockIdx.x * blockDim.x + threadIdx.x;
    if (e >= E) return;
    int d = dst[e];
    int p = atomicAdd(&g_work[d], 1);
    g_csr[p] = src[e];
}

// ---------------- tf32 MMA GEMM (R9, unchanged) ----------------
template<bool ACT>
__global__ void __launch_bounds__(256, 1)
k_gemm(const float* __restrict__ X, const float* __restrict__ W,
       const float* __restrict__ sc, const float* __restrict__ sh,
       const float* __restrict__ a_src, const float* __restrict__ a_dst,
       __half* __restrict__ Y, int n) {
    extern __shared__ float smf[];
    float*    a_s   = smf;                         // 128 * A_STR floats
    unsigned* b_buf = (unsigned*)(smf + 128 * A_STR);  // 16384 u32
    float*    s_as  = (float*)(b_buf + 16384);     // 128
    float*    s_ad  = s_as + 128;                  // 128
    int t = threadIdx.x;
    int rb = blockIdx.x * 128;
    const float4* X4 = (const float4*)X;
    const float4* W4 = (const float4*)W;

    if (t < 128) { s_as[t] = a_src[t]; s_ad[t] = a_dst[t]; }

#pragma unroll
    for (int i = 0; i < 16; i++) {
        int q = i * 256 + t;
        int row = q >> 5, c4 = (q & 31) * 4;
        float4 v = make_float4(0.f, 0.f, 0.f, 0.f);
        if (rb + row < n) v = X4[(long)(rb + row) * 32 + (q & 31)];
        if (ACT) {
            v.x = elu_f(sc[c4 + 0] * v.x + sh[c4 + 0]);
            v.y = elu_f(sc[c4 + 1] * v.y + sh[c4 + 1]);
            v.z = elu_f(sc[c4 + 2] * v.z + sh[c4 + 2]);
            v.w = elu_f(sc[c4 + 3] * v.w + sh[c4 + 3]);
        }
        float4 tv;
        tv.x = __uint_as_float(f2tf32(v.x));
        tv.y = __uint_as_float(f2tf32(v.y));
        tv.z = __uint_as_float(f2tf32(v.z));
        tv.w = __uint_as_float(f2tf32(v.w));
        *(float4*)&a_s[row * A_STR + c4] = tv;
    }
#pragma unroll
    for (int i = 0; i < 16; i++) {
        int q = i * 256 + t;
        int k = q >> 5, c4 = (q & 31) * 4;
        float4 v = W4[q];
        const float* vf = (const float*)&v;
#pragma unroll
        for (int e = 0; e < 4; e++) {
            int ncol = c4 + e;
            int tile = (k >> 3) * 16 + (ncol >> 3);
            int lf = ((ncol & 7) << 2) | (k & 3);
            int j = (k & 7) >= 4 ? 1 : 0;
            int off = (lf * 2 + j) ^ ((tile & 15) << 1);
            b_buf[tile * 64 + off] = f2tf32(vf[e]);
        }
    }
    __syncthreads();

    int w = t >> 5, l = t & 31;
    int gr = l >> 2, gc = l & 3;
    float d[16][4];
#pragma unroll
    for (int nb = 0; nb < 16; nb++)
#pragma unroll
        for (int j = 0; j < 4; j++) d[nb][j] = 0.f;

    int arow = (w * 16 + gr) * A_STR + gc;
    for (int kb = 0; kb < 16; kb++) {
        int ab = arow + kb * 8;
        unsigned a0 = __float_as_uint(a_s[ab]);
        unsigned a1 = __float_as_uint(a_s[ab + 8 * A_STR]);
        unsigned a2 = __float_as_uint(a_s[ab + 4]);
        unsigned a3 = __float_as_uint(a_s[ab + 8 * A_STR + 4]);
#pragma unroll
        for (int nb = 0; nb < 16; nb++) {
            int tile = kb * 16 + nb;
            uint2 b = *(const uint2*)&b_buf[tile * 64 + ((l * 2) ^ (nb << 1))];
            asm volatile(
                "mma.sync.aligned.m16n8k8.row.col.f32.tf32.tf32.f32 "
                "{%0,%1,%2,%3}, {%4,%5,%6,%7}, {%8,%9}, {%0,%1,%2,%3};"
                : "+f"(d[nb][0]), "+f"(d[nb][1]), "+f"(d[nb][2]), "+f"(d[nb][3])
                : "r"(a0), "r"(a1), "r"(a2), "r"(a3), "r"(b.x), "r"(b.y));
        }
    }

    int r0g = rb + w * 16 + gr;
    int r1g = r0g + 8;
    int cb0 = gc * 2;
    float es0[4], es1[4], ed0[4], ed1[4];
#pragma unroll
    for (int hh = 0; hh < 4; hh++) { es0[hh] = 0.f; es1[hh] = 0.f; ed0[hh] = 0.f; ed1[hh] = 0.f; }
#pragma unroll
    for (int nb = 0; nb < 16; nb++) {
        int colb = nb * 8 + cb0;
        int hh = nb >> 2;
        float a0 = s_as[colb], a1 = s_as[colb + 1];
        float b0 = s_ad[colb], b1 = s_ad[colb + 1];
        es0[hh] += d[nb][0] * a0 + d[nb][1] * a1;
        es1[hh] += d[nb][2] * a0 + d[nb][3] * a1;
        ed0[hh] += d[nb][0] * b0 + d[nb][1] * b1;
        ed1[hh] += d[nb][2] * b0 + d[nb][3] * b1;
    }
#pragma unroll
    for (int o = 1; o <= 2; o <<= 1) {
#pragma unroll
        for (int hh = 0; hh < 4; hh++) {
            es0[hh] += __shfl_xor_sync(0xffffffffu, es0[hh], o);
            es1[hh] += __shfl_xor_sync(0xffffffffu, es1[hh], o);
            ed0[hh] += __shfl_xor_sync(0xffffffffu, ed0[hh], o);
            ed1[hh] += __shfl_xor_sync(0xffffffffu, ed1[hh], o);
        }
    }
    if (gc == 0) {
        if (r0g < n) {
            *(float4*)&g_es[r0g * HEADS] = make_float4(es0[0], es0[1], es0[2], es0[3]);
            *(float4*)&g_ed[r0g * HEADS] = make_float4(ed0[0], ed0[1], ed0[2], ed0[3]);
        }
        if (r1g < n) {
            *(float4*)&g_es[r1g * HEADS] = make_float4(es1[0], es1[1], es1[2], es1[3]);
            *(float4*)&g_ed[r1g * HEADS] = make_float4(ed1[0], ed1[1], ed1[2], ed1[3]);
        }
    }
    bool st0 = r0g < n, st1 = r1g < n;
#pragma unroll
    for (int nb = 0; nb < 16; nb++) {
        int colb = nb * 8 + cb0;
        if (st0) {
            __half2 hv = __floats2half2_rn(d[nb][0], d[nb][1]);
            *(unsigned*)&Y[(long)r0g * CH + colb] = *(unsigned*)&hv;
        }
        if (st1) {
            __half2 hv = __floats2half2_rn(d[nb][2], d[nb][3]);
            *(unsigned*)&Y[(long)r1g * CH + colb] = *(unsigned*)&hv;
        }
    }
}

// ---------------- persistent warp-per-dst attention + fused finalize (exact R9 body) ----------------
template<int LAYER>
__global__ void __launch_bounds__(256)
k_attn(const __half* __restrict__ h, const float* __restrict__ bias,
       float* __restrict__ bnsum, float* __restrict__ bnsq,
       int n, int nwarps) {
    __shared__ int   s_idx[8][32];
    __shared__ float s_w  [8][128];
    int wb = threadIdx.x >> 5, l = threadIdx.x & 31;
    int gw = blockIdx.x * 8 + wb;
    int hsel = l >> 3, cg = l * 4;
    float bs[4] = {0.f, 0.f, 0.f, 0.f};
    float bq[4] = {0.f, 0.f, 0.f, 0.f};

    for (int d = gw; d < n; d += nwarps) {
        int beg = g_rowptr[d], end = g_rowptr[d + 1];
        float4 ed4 = *(const float4*)&g_ed[d * HEADS];
        float4 esd = *(const float4*)&g_es[d * HEADS];
        float4 wsf;
        wsf.x = __expf(lrelu(esd.x + ed4.x));
        wsf.y = __expf(lrelu(esd.y + ed4.y));
        wsf.z = __expf(lrelu(esd.z + ed4.z));
        wsf.w = __expf(lrelu(esd.w + ed4.w));
        float wsh = hsel == 0 ? wsf.x : hsel == 1 ? wsf.y : hsel == 2 ? wsf.z : wsf.w;
        float4 acc = ld_h4(&h[(long)d * CH + cg]);
        acc.x *= wsh; acc.y *= wsh; acc.z *= wsh; acc.w *= wsh;
        float4 den = (l == 0) ? wsf : make_float4(0.f, 0.f, 0.f, 0.f);

        for (int j0 = beg; j0 < end; j0 += 32) {
            int j = j0 + l;
            int s = 0;
            float4 w4 = make_float4(0.f, 0.f, 0.f, 0.f);
            if (j < end) {
                s = g_csr[j];
                float4 es4 = *(const float4*)&g_es[s * HEADS];
                w4.x = __expf(lrelu(es4.x + ed4.x));
                w4.y = __expf(lrelu(es4.y + ed4.y));
                w4.z = __expf(lrelu(es4.z + ed4.z));
                w4.w = __expf(lrelu(es4.w + ed4.w));
            }
            den.x += w4.x; den.y += w4.y; den.z += w4.z; den.w += w4.w;
            s_idx[wb][l] = s;
            *(float4*)&s_w[wb][l * 4] = w4;
            __syncwarp();
            int kmax = min(32, end - j0);
#pragma unroll 4
            for (int k = 0; k < kmax; k++) {
                int   sk = s_idx[wb][k];
                float w  = s_w[wb][k * 4 + hsel];
                float4 hv = ld_h4(&h[(long)sk * CH + cg]);
                acc.x += w * hv.x; acc.y += w * hv.y;
                acc.z += w * hv.z; acc.w += w * hv.w;
            }
            __syncwarp();
        }
#pragma unroll
        for (int o = 16; o; o >>= 1) {
            den.x += __shfl_xor_sync(0xffffffffu, den.x, o);
            den.y += __shfl_xor_sync(0xffffffffu, den.y, o);
            den.z += __shfl_xor_sync(0xffffffffu, den.z, o);
            den.w += __shfl_xor_sync(0xffffffffu, den.w, o);
        }
        float dh = hsel == 0 ? den.x : hsel == 1 ? den.y : hsel == 2 ? den.z : den.w;
        float rd = 1.f / dh;
        if (LAYER == 1) {
            float4 b4 = *(const float4*)&bias[cg];
            float4 v;
            v.x = acc.x * rd + b4.x; v.y = acc.y * rd + b4.y;
            v.z = acc.z * rd + b4.z; v.w = acc.w * rd + b4.w;
            *(float4*)&g_acc[(long)d * CH + cg] = v;
            bs[0] += v.x; bs[1] += v.y; bs[2] += v.z; bs[3] += v.w;
            bq[0] += v.x * v.x; bq[1] += v.y * v.y; bq[2] += v.z * v.z; bq[3] += v.w * v.w;
        } else {
            float4 v;
            v.x = acc.x * rd; v.y = acc.y * rd; v.z = acc.z * rd; v.w = acc.w * rd;
#pragma unroll
            for (int o = 8; o <= 16; o <<= 1) {
                v.x += __shfl_xor_sync(0xffffffffu, v.x, o);
                v.y += __shfl_xor_sync(0xffffffffu, v.y, o);
                v.z += __shfl_xor_sync(0xffffffffu, v.z, o);
                v.w += __shfl_xor_sync(0xffffffffu, v.w, o);
            }
            if (l < 8) {
                float4 b4 = *(const float4*)&bias[l * 4];
                v.x = 0.25f * v.x + b4.x; v.y = 0.25f * v.y + b4.y;
                v.z = 0.25f * v.z + b4.z; v.w = 0.25f * v.w + b4.w;
                *(float4*)&g_z[(long)d * FEAT + l * 4] = v;
                bs[0] += v.x; bs[1] += v.y; bs[2] += v.z; bs[3] += v.w;
                bq[0] += v.x * v.x; bq[1] += v.y * v.y; bq[2] += v.z * v.z; bq[3] += v.w * v.w;
            }
        }
    }
    if (LAYER == 1 || l < 8) {
        int c0 = (LAYER == 1) ? cg : l * 4;
#pragma unroll
        for (int j = 0; j < 4; j++) {
            atomicAdd(&bnsum[c0 + j], bs[j]);
            atomicAdd(&bnsq [c0 + j], bq[j]);
        }
    }
}

// ---------------- BN scale/shift prep ----------------
__global__ void k_bnprep(const float* __restrict__ gamma, const float* __restrict__ beta,
                         const float* __restrict__ bnsum, const float* __restrict__ bnsq,
                         float* __restrict__ sc, float* __restrict__ sh,
                         int C, float inv_n) {
    int c = threadIdx.x;
    if (c >= C) return;
    float mean = bnsum[c] * inv_n;
    float var  = bnsq[c] * inv_n - mean * mean;
    float g = gamma[c] * rsqrtf(var + BN_EPS);
    sc[c] = g;
    sh[c] = beta[c] - mean * g;
}

// ---------------- pool with fused BN+ELU ----------------
__global__ void k_pool(const int* __restrict__ batch, int n) {
    int i = blockIdx.x * blockDim.x + threadIdx.x;
    if (i >= n) return;
    int g = batch[i];
    const float4* zp = (const float4*)&g_z[(long)i * FEAT];
#pragma unroll
    for (int c = 0; c < 8; c++) {
        float4 z = zp[c];
        int c0 = c * 4;
        z.x = elu_f(g_sc2[c0 + 0] * z.x + g_sh2[c0 + 0]);
        z.y = elu_f(g_sc2[c0 + 1] * z.y + g_sh2[c0 + 1]);
        z.z = elu_f(g_sc2[c0 + 2] * z.z + g_sh2[c0 + 2]);
        z.w = elu_f(g_sc2[c0 + 3] * z.w + g_sh2[c0 + 3]);
        red_add_v4(&g_pool[g * FEAT + c0], z);
    }
    atomicAdd(&g_cnt[g], 1.f);
}

__global__ void k_final(const float* __restrict__ Wl, const float* __restrict__ bl,
                        float* __restrict__ out, int G) {
    int idx = blockIdx.x * blockDim.x + threadIdx.x;
    if (idx >= G * 2) return;
    int g = idx >> 1, o = idx & 1;
    float cn = fmaxf(g_cnt[g], 1.f);
    float s = bl[o];
#pragma unroll
    for (int f = 0; f < FEAT; f++)
        s += (g_pool[g * FEAT + f] / cn) * Wl[f * 2 + o];
    out[idx] = s;
}

// ---------------- host launch ----------------
extern "C" void kernel_launch(void* const* d_in, const int* in_sizes, int n_in,
                              void* d_out, int out_size) {
    const float* x   = (const float*)d_in[0];
    const int*   ei  = (const int*)  d_in[1];
    const int*   bat = (const int*)  d_in[2];
    const float* W1  = (const float*)d_in[3];
    const float* as1 = (const float*)d_in[4];
    const float* ad1 = (const float*)d_in[5];
    const float* b1  = (const float*)d_in[6];
    const float* g1  = (const float*)d_in[7];
    const float* be1 = (const float*)d_in[8];
    const float* W2  = (const float*)d_in[9];
    const float* as2 = (const float*)d_in[10];
    const float* ad2 = (const float*)d_in[11];
    const float* b2  = (const float*)d_in[12];
    const float* g2  = (const float*)d_in[13];
    const float* be2 = (const float*)d_in[14];
    const float* Wl  = (const float*)d_in[15];
    const float* bl  = (const float*)d_in[16];
    float* out = (float*)d_out;

    int n = in_sizes[0] / CH;   // 100000
    int E = in_sizes[1] / 2;    // 1600000
    int G = out_size / 2;       // 512
    const int* esrc = ei;
    const int* edst = ei + E;

    static __half* phh = nullptr;
    static float *pacc;
    static float *psc1, *psh1, *psc2, *psh2;
    static float *pbs1, *pbq1, *pbs2, *pbq2;
    static cudaStream_t s2;
    static cudaEvent_t ev_fork, ev_join;
    static bool configured = false;
    size_t gsmem = (size_t)128 * A_STR * 4 + 16384 * 4 + 256 * 4;  // ~134 KB
    if (!configured) {
        cudaGetSymbolAddress((void**)&phh,  g_hh);
        cudaGetSymbolAddress((void**)&pacc, g_acc);
        cudaGetSymbolAddress((void**)&psc1, g_sc1);
        cudaGetSymbolAddress((void**)&psh1, g_sh1);
        cudaGetSymbolAddress((void**)&psc2, g_sc2);
        cudaGetSymbolAddress((void**)&psh2, g_sh2);
        cudaGetSymbolAddress((void**)&pbs1, g_bnsum1);
        cudaGetSymbolAddress((void**)&pbq1, g_bnsq1);
        cudaGetSymbolAddress((void**)&pbs2, g_bnsum2);
        cudaGetSymbolAddress((void**)&pbq2, g_bnsq2);
        cudaFuncSetAttribute(k_gemm<false>, cudaFuncAttributeMaxDynamicSharedMemorySize, (int)gsmem);
        cudaFuncSetAttribute(k_gemm<true>,  cudaFuncAttributeMaxDynamicSharedMemorySize, (int)gsmem);
        cudaStreamCreateWithFlags(&s2, cudaStreamNonBlocking);
        cudaEventCreateWithFlags(&ev_fork, cudaEventDisableTiming);
        cudaEventCreateWithFlags(&ev_join, cudaEventDisableTiming);
        configured = true;
    }

    float inv_n = 1.f / (float)n;
    int nb_node = (n + 255) / 256;
    int nb_edge = (E + 255) / 256;
    int nb_gemm = (n + 127) / 128;
    int nb_attn = 592;                     // 4 blocks/SM x 148 (proven best)
    int nwarps  = nb_attn * 8;
    int B_scan  = (n + SCAN_CHUNK - 1) / SCAN_CHUNK;

    // fork at t=0: s2 = deg-zero + CSR chain; main = bulk-zero + GEMM-1 (concurrent)
    cudaEventRecord(ev_fork, 0);
    cudaStreamWaitEvent(s2, ev_fork, 0);
    k_zero_deg<<<nb_node, 256, 0, s2>>>(n);
    k_hist    <<<nb_edge, 256, 0, s2>>>(edst, E);
    k_scan1   <<<B_scan, SCAN_CHUNK, 0, s2>>>(n);
    k_scan2   <<<1, 32, 0, s2>>>(B_scan);
    k_scan3   <<<(n + 256) / 256, 256, 0, s2>>>(n);
    k_scatter <<<nb_edge, 256, 0, s2>>>(esrc, edst, E);
    cudaEventRecord(ev_join, s2);

    // ---- layer 1 ----
    k_zero_rest<<<(GMAX * FEAT + 255) / 256, 256>>>();
    k_gemm<false><<<nb_gemm, 256, gsmem>>>(x, W1, nullptr, nullptr, as1, ad1, phh, n);
    cudaStreamWaitEvent(0, ev_join, 0);
    k_attn<1><<<nb_attn, 256>>>(phh, b1, pbs1, pbq1, n, nwarps);
    k_bnprep<<<1, CH>>>(g1, be1, pbs1, pbq1, psc1, psh1, CH, inv_n);

    // ---- layer 2 (BN+ELU of layer1 fused into GEMM load) ----
    k_gemm<true><<<nb_gemm, 256, gsmem>>>(pacc, W2, psc1, psh1, as2, ad2, phh, n);
    k_attn<2><<<nb_attn, 256>>>(phh, b2, pbs2, pbq2, n, nwarps);
    k_bnprep<<<1, FEAT>>>(g2, be2, pbs2, pbq2, psc2, psh2, FEAT, inv_n);

    // ---- pool (BN+ELU fused) + linear ----
    k_pool<<<nb_node, 256>>>(bat, n);
    k_final<<<(G * 2 + 255) / 256, 256>>>(Wl, bl, out, G);
}